// round 14
// baseline (speedup 1.0000x reference)
#include <cuda_runtime.h>
#include <cuda_fp16.h>
#include <cstdint>

// Problem constants: B=8, N=8192, D=256, K=3
#define BB 8
#define NN 8192
#define DD 256
#define KK 3
#define TOKENS (BB * NN)            // 65536

#define CTA_M 128                   // tokens per CTA
#define KC 32                       // contract chunk
#define NCHUNK 24                   // full contract: 768 / 32
#define S_STRIDE 40                 // halves; proven conflict-free (R7)
#define AST 132                     // Asf stride (f32): [k][tok]
#define BFT 36                      // Bf stride (f32): [k][col]
#define TAP_BLOCKS (TOKENS / 8)

struct Tap { int fi, ci; float cf, cc; };

// __device__ scratch (no allocation allowed)
__device__ Tap    d_taps[TOKENS * KK];        // 3 MB
__device__ __half d_Wh[DD * KK * DD];         // 384 KB: d_Wh[n][tap*256+e]
__device__ float  d_Wf[KK * DD * 64];         // 192 KB: d_Wf[k768][nh*32+cc], cols 96..127 per half

#define BARRIER() asm volatile("bar.sync 0;" ::: "memory")

__device__ __forceinline__ void mma_f16(float* c, const uint32_t* a,
                                        uint32_t b0, uint32_t b1) {
    asm volatile(
        "mma.sync.aligned.m16n8k16.row.col.f32.f16.f16.f32 "
        "{%0,%1,%2,%3}, {%4,%5,%6,%7}, {%8,%9}, {%0,%1,%2,%3};"
        : "+f"(c[0]), "+f"(c[1]), "+f"(c[2]), "+f"(c[3])
        : "r"(a[0]), "r"(a[1]), "r"(a[2]), "r"(a[3]), "r"(b0), "r"(b1));
}

// gather 16 interpolated f32 at contract offset e (full fp32)
__device__ __forceinline__ void gather16(float4* pa, const float* __restrict__ xb,
                                         Tap t, int e) {
    const float4* pf = (const float4*)(xb + t.fi * DD + e);
    const float4* pc = (const float4*)(xb + t.ci * DD + e);
#pragma unroll
    for (int j = 0; j < 4; ++j) {
        float4 vf = pf[j], vc = pc[j];
        pa[j].x = fmaf(t.cf, vf.x, t.cc * vc.x);
        pa[j].y = fmaf(t.cf, vf.y, t.cc * vc.y);
        pa[j].z = fmaf(t.cf, vf.z, t.cc * vc.z);
        pa[j].w = fmaf(t.cf, vf.w, t.cc * vc.w);
    }
}

// ---------------------------------------------------------------------------
// Kernel 1 (fused): blocks < TAP_BLOCKS compute per-token taps (proven R6-R11);
// remaining 256 blocks build d_Wh (half, all cols) and d_Wf (fp32, cols 96..127
// of each 128-col half, locally indexed nh*32 + (n & 31)).
// ---------------------------------------------------------------------------
__global__ void taps_build_kernel(const float* __restrict__ x,
                                  const float* __restrict__ ow,
                                  const float* __restrict__ mw,
                                  const float* __restrict__ w) {
    if (blockIdx.x >= TAP_BLOCKS) {
        int idx = (blockIdx.x - TAP_BLOCKS) * 256 + threadIdx.x;
        if (idx >= DD * DD) return;
        int n = idx >> 8, e = idx & 255;
        bool ff_col = (n & 127) >= 96;
        int lc = (n >> 7) * 32 + (n & 31);
#pragma unroll
        for (int tap = 0; tap < KK; ++tap) {
            float v = w[(n * DD + e) * KK + tap];
            d_Wh[n * (KK * DD) + tap * DD + e] = __float2half(v);
            if (ff_col) d_Wf[(tap * DD + e) * 64 + lc] = v;
        }
        return;
    }

    int gw   = (blockIdx.x * blockDim.x + threadIdx.x) >> 5;
    int lane = threadIdx.x & 31;

    const float* xr = x + (long long)gw * DD;
    float s0 = 0.f, s1 = 0.f, s2 = 0.f, s3 = 0.f, s4 = 0.f, s5 = 0.f;
#pragma unroll
    for (int i = 0; i < DD / 32; ++i) {
        int e = lane + (i << 5);
        float v = xr[e];
        s0 += v * __ldg(ow + e);
        s1 += v * __ldg(ow + DD + e);
        s2 += v * __ldg(ow + 2 * DD + e);
        s3 += v * __ldg(mw + e);
        s4 += v * __ldg(mw + DD + e);
        s5 += v * __ldg(mw + 2 * DD + e);
    }
#pragma unroll
    for (int off = 16; off > 0; off >>= 1) {
        s0 += __shfl_xor_sync(0xffffffffu, s0, off);
        s1 += __shfl_xor_sync(0xffffffffu, s1, off);
        s2 += __shfl_xor_sync(0xffffffffu, s2, off);
        s3 += __shfl_xor_sync(0xffffffffu, s3, off);
        s4 += __shfl_xor_sync(0xffffffffu, s4, off);
        s5 += __shfl_xor_sync(0xffffffffu, s5, off);
    }
    if (lane == 0) {
        int n = gw & (NN - 1);
        float offs[3] = { s0, s1, s2 };
        float mraw[3] = { s3, s4, s5 };
#pragma unroll
        for (int k = 0; k < KK; ++k) {
            float pos = (float)(n + k - 1) + offs[k];
            float m   = 1.0f / (1.0f + expf(-mraw[k]));
            bool valid = (pos >= 0.0f) && (pos < (float)NN);
            float ff = floorf(pos);
            ff = fminf(fmaxf(ff, 0.0f), (float)(NN - 1));
            int fi = (int)ff;
            int ci = min(fi + 1, NN - 1);
            float wc = pos - ff;
            float coef = valid ? m : 0.0f;
            Tap t;
            t.fi = fi; t.ci = ci;
            t.cf = coef * (1.0f - wc);
            t.cc = coef * wc;
            d_taps[gw * KK + k] = t;
        }
    }
}

// ---------------------------------------------------------------------------
// Kernel 2: warp-specialized gather-GEMM — pure n-split, FULL 768-k contract
// on both paths.
//   Warps 0-7 : f16 m16n8k16 MMA, cols 0..95 (warp tile 32x48); also gather A
//               and store it as half (As) AND fp32 (Asf).
//   Warps 8-15: pure-fp32 FFMA2 path, cols 96..127, reading Asf + Bf; also the
//               Bs/Bf loaders. All issue hides in the MMA warps' 32-cyc stalls.
// ---------------------------------------------------------------------------
__global__ __launch_bounds__(512, 1)
void gemm_ws_kernel(const float* __restrict__ x, float* __restrict__ out) {
    __shared__ __align__(16) __half As[CTA_M * S_STRIDE];   // 10 KB  A half
    __shared__ __align__(16) __half Bs[128 * S_STRIDE];     // 10 KB  B half
    __shared__ __align__(16) float  Asf[KC * AST];          // 16.9KB A fp32 [k][tok]
    __shared__ __align__(16) float  Bf[KC * BFT];           // 4.6 KB B fp32 [k][col]

    const int tid  = threadIdx.x;
    const int wid  = tid >> 5;
    const int lane = tid & 31;
    const int tile = blockIdx.x >> 1;
    const int nh   = blockIdx.x & 1;
    const int tok0 = tile * CTA_M;
    const int b    = tok0 >> 13;
    const float* xb = x + (size_t)b * NN * DD;

    if (wid < 8) {
        // ================= MMA role (cols 0..95) + A loader =================
        const int wm  = wid & 3;
        const int wn  = wid >> 2;
        const int grp = lane >> 2;
        const int tg  = lane & 3;
        const int a_tok = tid & 127;
        const int ah    = tid >> 7;       // k-half (0/1)

        Tap t0 = d_taps[(tok0 + a_tok) * KK + 0];
        Tap t1 = d_taps[(tok0 + a_tok) * KK + 1];
        Tap t2 = d_taps[(tok0 + a_tok) * KK + 2];

        float acc[2][6][4];
#pragma unroll
        for (int mi = 0; mi < 2; ++mi)
#pragma unroll
            for (int ni = 0; ni < 6; ++ni)
#pragma unroll
                for (int j = 0; j < 4; ++j) acc[mi][ni][j] = 0.0f;

        float4 pa[4];
        gather16(pa, xb, t0, ah * 16);    // chunk 0

        for (int it = 0; it < NCHUNK; ++it) {
            BARRIER();
            // store A fp32 (for FFMA warps) and half (for MMA)
            {
                const float* pv = (const float*)pa;
#pragma unroll
                for (int j = 0; j < 16; ++j)
                    Asf[(ah * 16 + j) * AST + a_tok] = pv[j];

                uint4 ha;
                __half2* hp = (__half2*)&ha;
                hp[0] = __floats2half2_rn(pa[0].x, pa[0].y);
                hp[1] = __floats2half2_rn(pa[0].z, pa[0].w);
                hp[2] = __floats2half2_rn(pa[1].x, pa[1].y);
                hp[3] = __floats2half2_rn(pa[1].z, pa[1].w);
                *(uint4*)&As[a_tok * S_STRIDE + ah * 16] = ha;
                hp[0] = __floats2half2_rn(pa[2].x, pa[2].y);
                hp[1] = __floats2half2_rn(pa[2].z, pa[2].w);
                hp[2] = __floats2half2_rn(pa[3].x, pa[3].y);
                hp[3] = __floats2half2_rn(pa[3].z, pa[3].w);
                *(uint4*)&As[a_tok * S_STRIDE + ah * 16 + 8] = ha;
            }
            BARRIER();
            // prefetch next A chunk
            if (it + 1 < NCHUNK) {
                const int cn  = it + 1;
                const int tap = cn >> 3;
                const int e0  = (cn & 7) << 5;
                Tap t = (tap == 0) ? t0 : (tap == 1) ? t1 : t2;
                gather16(pa, xb, t, e0 + ah * 16);
            }
            // MMA compute: 2 k16 steps x 2 mi x 6 ni
#pragma unroll
            for (int ks = 0; ks < 2; ++ks) {
                const int k0 = ks * 16;
                uint32_t afr[2][4];
#pragma unroll
                for (int mi = 0; mi < 2; ++mi) {
                    int row = wm * 32 + mi * 16;
                    afr[mi][0] = *(const uint32_t*)&As[(row + grp    ) * S_STRIDE + k0 + 2 * tg    ];
                    afr[mi][1] = *(const uint32_t*)&As[(row + grp + 8) * S_STRIDE + k0 + 2 * tg    ];
                    afr[mi][2] = *(const uint32_t*)&As[(row + grp    ) * S_STRIDE + k0 + 2 * tg + 8];
                    afr[mi][3] = *(const uint32_t*)&As[(row + grp + 8) * S_STRIDE + k0 + 2 * tg + 8];
                }
#pragma unroll
                for (int ni = 0; ni < 6; ++ni) {
                    int col = wn * 48 + ni * 8 + grp;
                    uint32_t b0 = *(const uint32_t*)&Bs[col * S_STRIDE + k0 + 2 * tg    ];
                    uint32_t b1 = *(const uint32_t*)&Bs[col * S_STRIDE + k0 + 2 * tg + 8];
                    mma_f16(acc[0][ni], afr[0], b0, b1);
                    mma_f16(acc[1][ni], afr[1], b0, b1);
                }
            }
        }

        // epilogue: cols nh*128 + wn*48 + ...
#pragma unroll
        for (int mi = 0; mi < 2; ++mi) {
            size_t row = (size_t)tok0 + wm * 32 + mi * 16 + grp;
            float* op0 = out + row * DD + nh * 128 + wn * 48;
            float* op1 = op0 + 8 * DD;
#pragma unroll
            for (int ni = 0; ni < 6; ++ni) {
                int col = ni * 8 + tg * 2;
                float2 v0 = { acc[mi][ni][0], acc[mi][ni][1] };
                float2 v1 = { acc[mi][ni][2], acc[mi][ni][3] };
                *(float2*)(op0 + col) = v0;
                *(float2*)(op1 + col) = v1;
            }
        }
    } else {
        // ============ FFMA role (cols 96..127, full contract) + B loaders ============
        const int f  = wid - 8;           // warp: tokens f*16..f*16+15
        const int tl = lane & 1;          // token octet
        const int cl = lane >> 1;         // col pair 96+2cl
        const int u  = tid - 256;
        const int b_tok = u >> 1;         // Bs loader row (= col index)
        const int bh    = u & 1;
        const int fk    = u >> 3;         // Bf loader k (0..31)
        const int fcg   = u & 7;          // Bf loader col group (4 cols)

        const __half* whb = d_Wh + (size_t)(nh * 128 + b_tok) * (KK * DD) + bh * 16;

        unsigned long long accf[8];
#pragma unroll
        for (int j = 0; j < 8; ++j) accf[j] = 0ull;

        uint4  pb0, pb1;
        float4 pfb;

        // prologue: Bs chunk 0, Bf chunk 0
        {
            const uint4* bsrc = (const uint4*)whb;
            pb0 = bsrc[0]; pb1 = bsrc[1];
            pfb = *(const float4*)&d_Wf[(size_t)fk * 64 + nh * 32 + fcg * 4];
        }

        const int abase = f * 16 + tl * 8;
        const int cbase = 2 * cl;

        for (int it = 0; it < NCHUNK; ++it) {
            BARRIER();
            // store B tiles
            *(uint4*)&Bs[b_tok * S_STRIDE + bh * 16]     = pb0;
            *(uint4*)&Bs[b_tok * S_STRIDE + bh * 16 + 8] = pb1;
            *(float4*)&Bf[fk * BFT + fcg * 4] = pfb;
            BARRIER();
            // prefetch next chunk
            if (it + 1 < NCHUNK) {
                const uint4* bsrc = (const uint4*)(whb + (it + 1) * KC);
                pb0 = bsrc[0]; pb1 = bsrc[1];
                pfb = *(const float4*)&d_Wf[((size_t)(it + 1) * KC + fk) * 64
                                            + nh * 32 + fcg * 4];
            }
            // FFMA compute: full 32-k chunk on the fp32 pipe
#pragma unroll 8
            for (int k = 0; k < KC; ++k) {
                unsigned long long a2[4];
#pragma unroll
                for (int p = 0; p < 4; ++p)
                    a2[p] = *(const unsigned long long*)(Asf + k * AST + abase + 2 * p);
                float2 bp = *(const float2*)(Bf + k * BFT + cbase);
                unsigned long long b0d, b1d;
                asm("mov.b64 %0, {%1, %1};" : "=l"(b0d) : "f"(bp.x));
                asm("mov.b64 %0, {%1, %1};" : "=l"(b1d) : "f"(bp.y));
#pragma unroll
                for (int p = 0; p < 4; ++p) {
                    asm("fma.rn.f32x2 %0, %1, %2, %0;"
                        : "+l"(accf[2 * p + 0]) : "l"(a2[p]), "l"(b0d));
                    asm("fma.rn.f32x2 %0, %1, %2, %0;"
                        : "+l"(accf[2 * p + 1]) : "l"(a2[p]), "l"(b1d));
                }
            }
        }

        // epilogue: tokens abase+{0..7}, cols nh*128 + 96 + 2cl + {0,1}
        {
            const size_t tokb = (size_t)tok0 + abase;
            float* ob = out + tokb * DD + nh * 128 + 96 + 2 * cl;
#pragma unroll
            for (int p = 0; p < 4; ++p) {
                uint32_t l0, h0, l1, h1;
                asm("mov.b64 {%0, %1}, %2;" : "=r"(l0), "=r"(h0) : "l"(accf[2 * p + 0]));
                asm("mov.b64 {%0, %1}, %2;" : "=r"(l1), "=r"(h1) : "l"(accf[2 * p + 1]));
                float2 v0 = { __uint_as_float(l0), __uint_as_float(l1) };
                float2 v1 = { __uint_as_float(h0), __uint_as_float(h1) };
                *(float2*)(ob + (size_t)(2 * p) * DD)     = v0;
                *(float2*)(ob + (size_t)(2 * p + 1) * DD) = v1;
            }
        }
    }
}

// ---------------------------------------------------------------------------
// Launch (graph-capturable: kernel launches only)
// ---------------------------------------------------------------------------
extern "C" void kernel_launch(void* const* d_in, const int* in_sizes, int n_in,
                              void* d_out, int out_size) {
    const float* x  = (const float*)d_in[0];
    const float* ow = (const float*)d_in[1];
    const float* mw = (const float*)d_in[2];
    const float* w  = (const float*)d_in[3];
    float* out = (float*)d_out;
    (void)in_sizes; (void)n_in; (void)out_size;

    taps_build_kernel<<<TAP_BLOCKS + 256, 256>>>(x, ow, mw, w);
    gemm_ws_kernel<<<(TOKENS / CTA_M) * 2, 512>>>(x, out);
}

// round 16
// speedup vs baseline: 2.1798x; 2.1798x over previous
#include <cuda_runtime.h>
#include <cuda_fp16.h>
#include <cstdint>

// Problem constants: B=8, N=8192, D=256, K=3
#define BB 8
#define NN 8192
#define DD 256
#define KK 3
#define TOKENS (BB * NN)            // 65536

#define CTA_M 128                   // tokens per CTA (full 256 output cols)
#define KC 32                       // contract chunk
#define NCHUNK 24                   // 768 / 32
#define S_STRIDE 40                 // halves; proven conflict-free (R7)

struct Tap { int fi, ci; float cf, cc; };

// __device__ scratch (no allocation allowed)
__device__ __half d_Wh[DD * KK * DD];         // 384 KB: d_Wh[n][tap*256+e]

__device__ __forceinline__ void mma_f16(float* c, const uint32_t* a,
                                        uint32_t b0, uint32_t b1) {
    asm volatile(
        "mma.sync.aligned.m16n8k16.row.col.f32.f16.f16.f32 "
        "{%0,%1,%2,%3}, {%4,%5,%6,%7}, {%8,%9}, {%0,%1,%2,%3};"
        : "+f"(c[0]), "+f"(c[1]), "+f"(c[2]), "+f"(c[3])
        : "r"(a[0]), "r"(a[1]), "r"(a[2]), "r"(a[3]), "r"(b0), "r"(b1));
}

// ---------------------------------------------------------------------------
// Kernel 1: B matrix build. d_Wh[n*768 + tap*256 + e] = half(weight[n][e][tap]).
// ---------------------------------------------------------------------------
__global__ void build_b_kernel(const float* __restrict__ w) {
    int idx = blockIdx.x * blockDim.x + threadIdx.x;   // (n, e)
    if (idx >= DD * DD) return;
    int n = idx >> 8, e = idx & 255;
#pragma unroll
    for (int tap = 0; tap < KK; ++tap)
        d_Wh[n * (KK * DD) + tap * DD + e] = __float2half(w[(n * DD + e) * KK + tap]);
}

// ---------------------------------------------------------------------------
// Kernel 2: fully fused taps + gather + f16 mma.sync GEMM.
// CTA: 128 tokens x 256 cols, 512 threads, 16 warps = 4m x 4n (tile 32x64).
// Prologue: warp w computes taps for tokens w*8..w*8+7 (warp-dot + shfl).
// Main loop: R7's proven single-buffer register-prefetch chunk loop; A gathered
// ONCE per token (no n-half duplication), B streamed from d_Wh (L2-resident).
// ---------------------------------------------------------------------------
__global__ __launch_bounds__(512, 1)
void gemm_fused_kernel(const float* __restrict__ x,
                       const float* __restrict__ ow,
                       const float* __restrict__ mw,
                       float* __restrict__ out) {
    __shared__ __align__(16) __half As[CTA_M * S_STRIDE];   // 10 KB
    __shared__ __align__(16) __half Bs[256 * S_STRIDE];     // 20 KB
    __shared__ Tap s_taps[CTA_M * KK];                      // 1.5 KB

    const int tid  = threadIdx.x;
    const int wid  = tid >> 5;
    const int lane = tid & 31;
    const int tok0 = blockIdx.x * CTA_M;
    const int b    = tok0 >> 13;
    const float* xb = x + (size_t)b * NN * DD;

    // ============ Prologue: per-CTA tap computation (warp w -> 8 tokens) ============
#pragma unroll 1
    for (int tt = 0; tt < 8; ++tt) {
        const int tok = wid * 8 + tt;                 // 0..127
        const int gw  = tok0 + tok;
        const float* xr = x + (size_t)gw * DD;
        float s0 = 0.f, s1 = 0.f, s2 = 0.f, s3 = 0.f, s4 = 0.f, s5 = 0.f;
#pragma unroll
        for (int i = 0; i < DD / 32; ++i) {
            int e = lane + (i << 5);
            float v = xr[e];
            s0 += v * __ldg(ow + e);
            s1 += v * __ldg(ow + DD + e);
            s2 += v * __ldg(ow + 2 * DD + e);
            s3 += v * __ldg(mw + e);
            s4 += v * __ldg(mw + DD + e);
            s5 += v * __ldg(mw + 2 * DD + e);
        }
#pragma unroll
        for (int off = 16; off > 0; off >>= 1) {
            s0 += __shfl_xor_sync(0xffffffffu, s0, off);
            s1 += __shfl_xor_sync(0xffffffffu, s1, off);
            s2 += __shfl_xor_sync(0xffffffffu, s2, off);
            s3 += __shfl_xor_sync(0xffffffffu, s3, off);
            s4 += __shfl_xor_sync(0xffffffffu, s4, off);
            s5 += __shfl_xor_sync(0xffffffffu, s5, off);
        }
        if (lane == 0) {
            const int n = gw & (NN - 1);
            float offs[3] = { s0, s1, s2 };
            float mraw[3] = { s3, s4, s5 };
#pragma unroll
            for (int k = 0; k < KK; ++k) {
                float pos = (float)(n + k - 1) + offs[k];
                float m   = 1.0f / (1.0f + expf(-mraw[k]));
                bool valid = (pos >= 0.0f) && (pos < (float)NN);
                float ff = floorf(pos);
                ff = fminf(fmaxf(ff, 0.0f), (float)(NN - 1));
                int fi = (int)ff;
                int ci = min(fi + 1, NN - 1);
                float wc = pos - ff;
                float coef = valid ? m : 0.0f;
                Tap t;
                t.fi = fi; t.ci = ci;
                t.cf = coef * (1.0f - wc);
                t.cc = coef * wc;
                s_taps[tok * KK + k] = t;
            }
        }
    }
    __syncthreads();

    // ============ Roles ============
    const int wm  = wid & 3;          // warp m-tile (32 rows)
    const int wn  = wid >> 2;         // warp n-tile (64 cols)
    const int grp = lane >> 2;
    const int tg  = lane & 3;

    // A-gather: 4 threads per token, 8 floats each
    const int a_tok = tid >> 2;       // 0..127
    const int aq    = tid & 3;        // quarter (8 halves)
    // B-load: 2 threads per col, 16 halves each
    const int b_col = tid >> 1;       // 0..255
    const int bh    = tid & 1;

    Tap t0 = s_taps[a_tok * KK + 0];
    Tap t1 = s_taps[a_tok * KK + 1];
    Tap t2 = s_taps[a_tok * KK + 2];

    const __half* whb = d_Wh + (size_t)b_col * (KK * DD) + bh * 16;

    float acc[2][8][4];
#pragma unroll
    for (int mi = 0; mi < 2; ++mi)
#pragma unroll
        for (int ni = 0; ni < 8; ++ni)
#pragma unroll
            for (int j = 0; j < 4; ++j) acc[mi][ni][j] = 0.0f;

    float4 pa[2];     // prefetched interpolated A (8 f32)
    uint4  pb[2];     // prefetched B (16 halves)

    // prologue loads: chunk 0
    {
        const float4* pf = (const float4*)(xb + t0.fi * DD + aq * 8);
        const float4* pc = (const float4*)(xb + t0.ci * DD + aq * 8);
#pragma unroll
        for (int j = 0; j < 2; ++j) {
            float4 vf = pf[j], vc = pc[j];
            pa[j].x = fmaf(t0.cf, vf.x, t0.cc * vc.x);
            pa[j].y = fmaf(t0.cf, vf.y, t0.cc * vc.y);
            pa[j].z = fmaf(t0.cf, vf.z, t0.cc * vc.z);
            pa[j].w = fmaf(t0.cf, vf.w, t0.cc * vc.w);
        }
        const uint4* bs = (const uint4*)whb;
        pb[0] = bs[0]; pb[1] = bs[1];
    }

    for (int c = 0; c < NCHUNK; ++c) {
        __syncthreads();   // previous chunk fully consumed

        // store prefetched tiles
        {
            uint2 ha;
            __half2* hp = (__half2*)&ha;
            hp[0] = __floats2half2_rn(pa[0].x, pa[0].y);
            hp[1] = __floats2half2_rn(pa[0].z, pa[0].w);
            uint2 hb;
            __half2* hq = (__half2*)&hb;
            hq[0] = __floats2half2_rn(pa[1].x, pa[1].y);
            hq[1] = __floats2half2_rn(pa[1].z, pa[1].w);
            uint4 hall = { ha.x, ha.y, hb.x, hb.y };
            *(uint4*)&As[a_tok * S_STRIDE + aq * 8] = hall;

            *(uint4*)&Bs[b_col * S_STRIDE + bh * 16]     = pb[0];
            *(uint4*)&Bs[b_col * S_STRIDE + bh * 16 + 8] = pb[1];
        }
        __syncthreads();   // tiles visible

        // prefetch chunk c+1 (hides under the MMA wall)
        if (c + 1 < NCHUNK) {
            const int cn  = c + 1;
            const int tap = cn >> 3;
            const int e0  = ((cn & 7) << 5) + aq * 8;
            Tap t = (tap == 0) ? t0 : (tap == 1) ? t1 : t2;
            const float4* pf = (const float4*)(xb + t.fi * DD + e0);
            const float4* pc = (const float4*)(xb + t.ci * DD + e0);
#pragma unroll
            for (int j = 0; j < 2; ++j) {
                float4 vf = pf[j], vc = pc[j];
                pa[j].x = fmaf(t.cf, vf.x, t.cc * vc.x);
                pa[j].y = fmaf(t.cf, vf.y, t.cc * vc.y);
                pa[j].z = fmaf(t.cf, vf.z, t.cc * vc.z);
                pa[j].w = fmaf(t.cf, vf.w, t.cc * vc.w);
            }
            const uint4* bs = (const uint4*)(whb + cn * KC);
            pb[0] = bs[0]; pb[1] = bs[1];
        }

        // MMA over current chunk: 2 k16 steps x 2 mi x 8 ni
#pragma unroll
        for (int ks = 0; ks < 2; ++ks) {
            const int k0 = ks * 16;
            uint32_t afr[2][4];
#pragma unroll
            for (int mi = 0; mi < 2; ++mi) {
                int row = wm * 32 + mi * 16;
                afr[mi][0] = *(const uint32_t*)&As[(row + grp    ) * S_STRIDE + k0 + 2 * tg    ];
                afr[mi][1] = *(const uint32_t*)&As[(row + grp + 8) * S_STRIDE + k0 + 2 * tg    ];
                afr[mi][2] = *(const uint32_t*)&As[(row + grp    ) * S_STRIDE + k0 + 2 * tg + 8];
                afr[mi][3] = *(const uint32_t*)&As[(row + grp + 8) * S_STRIDE + k0 + 2 * tg + 8];
            }
#pragma unroll
            for (int ni = 0; ni < 8; ++ni) {
                int col = wn * 64 + ni * 8 + grp;
                uint32_t b0 = *(const uint32_t*)&Bs[col * S_STRIDE + k0 + 2 * tg    ];
                uint32_t b1 = *(const uint32_t*)&Bs[col * S_STRIDE + k0 + 2 * tg + 8];
                mma_f16(acc[0][ni], afr[0], b0, b1);
                mma_f16(acc[1][ni], afr[1], b0, b1);
            }
        }
    }

    // epilogue: c0/c1 at (row, 2tg), c2/c3 at (row+8, 2tg)
#pragma unroll
    for (int mi = 0; mi < 2; ++mi) {
        size_t row = (size_t)tok0 + wm * 32 + mi * 16 + grp;
        float* op0 = out + row * DD + wn * 64;
        float* op1 = op0 + 8 * DD;
#pragma unroll
        for (int ni = 0; ni < 8; ++ni) {
            int col = ni * 8 + tg * 2;
            float2 v0 = { acc[mi][ni][0], acc[mi][ni][1] };
            float2 v1 = { acc[mi][ni][2], acc[mi][ni][3] };
            *(float2*)(op0 + col) = v0;
            *(float2*)(op1 + col) = v1;
        }
    }
}

// ---------------------------------------------------------------------------
// Launch (graph-capturable: kernel launches only)
// ---------------------------------------------------------------------------
extern "C" void kernel_launch(void* const* d_in, const int* in_sizes, int n_in,
                              void* d_out, int out_size) {
    const float* x  = (const float*)d_in[0];
    const float* ow = (const float*)d_in[1];
    const float* mw = (const float*)d_in[2];
    const float* w  = (const float*)d_in[3];
    float* out = (float*)d_out;
    (void)in_sizes; (void)n_in; (void)out_size;

    build_b_kernel<<<(DD * DD + 255) / 256, 256>>>(w);
    gemm_fused_kernel<<<TOKENS / CTA_M, 512>>>(x, ow, mw, out);
}